// round 12
// baseline (speedup 1.0000x reference)
#include <cuda_runtime.h>

#define NB     16
#define NP     65536
#define NPTS   (NB * NP)                            // 1048576 points
#define RAD_N  5
#define AZI_N  30
#define ELE_N  15
#define KSL    (ELE_N - 1)                          // 14 ele pair-slots
#define PLANE_SLOTS (AZI_N * KSL)                   // 420 slots per (b,r) plane
#define PLANE_OUTS  (AZI_N * ELE_N)                 // 450 out bins per plane
#define NPLANE (NB * RAD_N)                         // 80 planes
#define NSLOT  (NPLANE * PLANE_SLOTS)               // 33600 float4 2x2-slots

#define NTHR   256
#define NBLK   (NPTS / 4 / NTHR)                    // 1024 blocks, 4 pts/thread

// 2x2 pair-slot histogram: slot[b][r][a][k] (a circular, k=0..13) holds
// contributions to bins (a,k),(a,k+1),(a+1%30,k),(a+1%30,k+1) in (.x,.y,.z,.w).
// INVARIANT: all-zero at kernel entry (zero-init at module load; the fold tail
// re-zeros after reading, so every graph replay sees a clean table).
__device__ float4 g_slots[NSLOT];

// Completion ticketing. g_gen is monotone across replays; g_done self-resets.
__device__ unsigned g_done = 0;
__device__ unsigned g_gen  = 0;

__device__ __forceinline__ void red_add4(float4* a, float x, float y, float z, float w) {
    asm volatile("red.global.add.v4.f32 [%0], {%1, %2, %3, %4};"
                 :: "l"(a), "f"(x), "f"(y), "f"(z), "f"(w) : "memory");
}

__device__ __forceinline__ void scatter_point(float x, float y, float z, int b) {
    float r = sqrtf(x * x + y * y + z * z);
    if (r > 2.0f) return;   // reference culls r > DES_R

    float azi = atan2f(y, x);
    if (azi < 0.f) azi += 6.28318530717958647692f;
    float ce  = fminf(fmaxf(z / fmaxf(r, 1e-12f), -1.f), 1.f);
    float ele = acosf(ce);

    // radial pair: closed form of ref's half-bin boundary clamps
    float vr = r * 2.5f - 0.5f;
    int jr; float wr0, wr1;
    if (vr < 0.f)        { jr = 0; wr0 = 1.f; wr1 = 0.f; }
    else if (vr >= 4.f)  { jr = 3; wr0 = 0.f; wr1 = 5.f - vr; }
    else { jr = (int)vr; float f = vr - (float)jr; wr0 = 1.f - f; wr1 = f; }

    // azimuth pair: circular; slot sa covers bins (sa, sa+1 mod 30)
    float va = azi * (float)(AZI_N / 6.283185307179586) - 0.5f;
    float fj = floorf(va);
    int   j  = (int)fj;                 // in [-1, 29]
    float fa = va - fj;
    int sa = (j < 0) ? (AZI_N - 1) : j;
    float wa0 = 1.f - fa, wa1 = fa;

    // elevation pair: both-end half-bin clamps
    float ve = ele * (float)(ELE_N / 3.141592653589793) - 0.5f;
    int ke; float we0, we1;
    if (ve < 0.f)         { ke = 0;  we0 = 1.f; we1 = 0.f; }
    else if (ve >= 14.f)  { ke = 13; we0 = 0.f; we1 = 1.f; }
    else { ke = (int)ve; float f = ve - (float)ke; we0 = 1.f - f; we1 = f; }

    float p00 = wa0 * we0, p01 = wa0 * we1;
    float p10 = wa1 * we0, p11 = wa1 * we1;

    int s0 = ((b * RAD_N + jr) * AZI_N + sa) * KSL + ke;
    if (wr0 != 0.f)
        red_add4(&g_slots[s0], wr0 * p00, wr0 * p01, wr0 * p10, wr0 * p11);
    if (wr1 != 0.f)
        red_add4(&g_slots[s0 + PLANE_SLOTS], wr1 * p00, wr1 * p01, wr1 * p10, wr1 * p11);
}

__global__ void __launch_bounds__(NTHR) vox_kernel(const float* __restrict__ pts,
                                                   float* __restrict__ out) {
    __shared__ unsigned s_ticket;
    __shared__ float4 s[PLANE_SLOTS];

    // ---- Scatter: 4 points per thread via 3x float4 coalesced loads ----
    int g = blockIdx.x * NTHR + threadIdx.x;    // exact multiple, no guard
    const float4* p4 = (const float4*)pts;
    float4 A = __ldg(p4 + 3 * g);
    float4 B = __ldg(p4 + 3 * g + 1);
    float4 C = __ldg(p4 + 3 * g + 2);
    int b = (g * 4) >> 16;                      // 4 pts share batch (NP%4==0)

    scatter_point(A.x, A.y, A.z, b);
    scatter_point(A.w, B.x, B.y, b);
    scatter_point(B.z, B.w, C.x, b);
    scatter_point(C.y, C.z, C.w, b);

    // ---- Ticketing: last NPLANE blocks to finish become finishers ----
    __threadfence();          // make this block's reds globally visible
    __syncthreads();          // all warps' reds issued before ticket
    if (threadIdx.x == 0) {
        // read gen BEFORE taking the ticket (flip can only happen after the
        // last ticket is taken, so we can never miss it)
        unsigned old = *(volatile unsigned*)&g_gen;
        unsigned t   = atomicAdd(&g_done, 1u);
        s_ticket = t;
        if (t == NBLK - 1) {
            atomicExch(&g_done, 0u);     // self-reset for next replay
            __threadfence();
            atomicAdd(&g_gen, 1u);       // release: all scatters complete
        } else if (t >= NBLK - NPLANE) {
            // spin on plain volatile load (no L2-atomic contention)
            while (*(volatile unsigned*)&g_gen == old) { __nanosleep(32); }
        }
        __threadfence();                 // acquire
    }
    __syncthreads();
    unsigned ticket = s_ticket;
    if (ticket < NBLK - NPLANE) return;  // non-finishers exit, zero extra cost

    // ---- Fold tail: this block owns one (b,r) plane ----
    int plane = (int)(ticket - (NBLK - NPLANE));
    float4* gp = g_slots + plane * PLANE_SLOTS;
    for (int i = threadIdx.x; i < PLANE_SLOTS; i += NTHR) {
        float4 v = __ldcg(&gp[i]);       // bypass L1: reds update L2 only
        s[i] = v;
        __stcg(&gp[i], make_float4(0.f, 0.f, 0.f, 0.f));  // restore invariant
    }
    __syncthreads();

    for (int i = threadIdx.x; i < PLANE_OUTS; i += NTHR) {
        int e   = i % ELE_N;
        int a   = i / ELE_N;
        int am1 = (a == 0) ? (AZI_N - 1) : (a - 1);

        float v = 0.f;
        if (e < KSL) {
            v += s[a   * KSL + e].x;
            v += s[am1 * KSL + e].z;
        }
        if (e > 0) {
            v += s[a   * KSL + e - 1].y;
            v += s[am1 * KSL + e - 1].w;
        }
        out[plane * PLANE_OUTS + i] = v;
    }
}

extern "C" void kernel_launch(void* const* d_in, const int* in_sizes, int n_in,
                              void* d_out, int out_size) {
    const float* pts = (const float*)d_in[0];
    float* out = (float*)d_out;
    vox_kernel<<<NBLK, NTHR>>>(pts, out);
}